// round 2
// baseline (speedup 1.0000x reference)
#include <cuda_runtime.h>
#include <math.h>

#define NN   20000        // nodes
#define NE   320000       // edges (without self loops)
#define ETOT (NE + NN)    // edges + self loops
#define NGR  256          // graphs
#define FD   11           // node feature dim
#define FT   30           // tda feature dim
#define DH   128          // hidden
#define NH   4            // heads
#define NL   3            // layers
#define NT   6            // tasks

// ---------------- device scratch (static, no allocations) ----------------
// NOTE: these are referenced ONLY inside kernels — never passed as kernel
// arguments from host code (host-side symbol address is the host shadow).
__device__ float g_h[NN * DH];            // node features (in-place updated)
__device__ float g_hh[NN * NH * DH];      // per-head transformed features [N,512]
__device__ float g_as[NN * NH];           // alpha_src per node/head
__device__ float g_ad[NN * NH];           // alpha_dst per node/head
__device__ int   g_rowptr[NN + 1];
__device__ int   g_cnt[NN];               // counts, then scatter cursor
__device__ int   g_esrc[ETOT];            // src ids sorted by dst
__device__ int   g_gstart[NGR + 1];
__device__ float g_pool[NGR * 320];       // [mean(128) | max(128) | tda(64)]

// ---------------- CSR build ----------------
__global__ void k_zero_cnt() {
    int i = blockIdx.x * blockDim.x + threadIdx.x;
    if (i < NN) g_cnt[i] = 0;
}

__global__ void k_count(const int* __restrict__ ei) {
    int i = blockIdx.x * blockDim.x + threadIdx.x;
    if (i >= ETOT) return;
    int dst = (i < NE) ? ei[NE + i] : (i - NE);
    atomicAdd(&g_cnt[dst], 1);
}

__global__ void k_scan() {   // single block, 1024 threads, chunk=20
    __shared__ int ssum[1024];
    const int CH = 20;
    int tid = threadIdx.x;
    int base = tid * CH;
    int s = 0;
    for (int j = 0; j < CH; j++) {
        int idx = base + j;
        if (idx < NN) s += g_cnt[idx];
    }
    ssum[tid] = s;
    __syncthreads();
    for (int off = 1; off < 1024; off <<= 1) {
        int v = 0;
        if (tid >= off) v = ssum[tid - off];
        __syncthreads();
        ssum[tid] += v;
        __syncthreads();
    }
    int run = tid ? ssum[tid - 1] : 0;
    for (int j = 0; j < CH; j++) {
        int idx = base + j;
        if (idx < NN) {
            int c = g_cnt[idx];
            g_rowptr[idx] = run;
            run += c;
        }
    }
    if (tid == 1023) g_rowptr[NN] = ssum[1023];
}

__global__ void k_cursor() {
    int i = blockIdx.x * blockDim.x + threadIdx.x;
    if (i < NN) g_cnt[i] = g_rowptr[i];
}

__global__ void k_scatter(const int* __restrict__ ei) {
    int i = blockIdx.x * blockDim.x + threadIdx.x;
    if (i >= ETOT) return;
    int src, dst;
    if (i < NE) { src = ei[i]; dst = ei[NE + i]; }
    else        { src = i - NE; dst = i - NE; }
    int pos = atomicAdd(&g_cnt[dst], 1);
    g_esrc[pos] = src;
}

// graph boundaries from sorted batch array
__global__ void k_gstart(const int* __restrict__ batch) {
    int i = blockIdx.x * blockDim.x + threadIdx.x;
    if (i > NN) return;
    int b  = (i < NN) ? batch[i] : NGR;
    int bp = (i > 0) ? batch[i - 1] : -1;
    for (int g = bp + 1; g <= b && g <= NGR; g++) g_gstart[g] = i;
}

// ---------------- input projection: h = relu(x @ w_in + b_in) ----------------
__global__ void k_inproj(const float* __restrict__ x, const float* __restrict__ w,
                         const float* __restrict__ b) {
    int n = blockIdx.x, d = threadIdx.x;
    __shared__ float xs[FD];
    if (d < FD) xs[d] = x[n * FD + d];
    __syncthreads();
    float a = b[d];
#pragma unroll
    for (int k = 0; k < FD; k++) a += xs[k] * w[k * DH + d];
    g_h[n * DH + d] = fmaxf(a, 0.f);
}

// ---------------- tiled SGEMM: g_hh[M,512] = g_h[M,128] @ B[128,512] ----------------
__global__ __launch_bounds__(256) void k_gemm(const float* __restrict__ B) {
    __shared__ float As[16][132];   // transposed A tile, padded
    __shared__ float Bs[16][128];
    const float* A = g_h;
    float* C = g_hh;
    const int M = NN;
    int tid = threadIdx.x;
    int m0 = blockIdx.x * 128, n0 = blockIdx.y * 128;
    int tx = tid & 15, ty = tid >> 4;

    float acc[8][8];
#pragma unroll
    for (int i = 0; i < 8; i++)
#pragma unroll
        for (int j = 0; j < 8; j++) acc[i][j] = 0.f;

    int arow = tid >> 2;          // 0..63
    int akg  = (tid & 3) * 4;     // k sub-offset
    int brow = tid >> 5;          // 0..7
    int bcol = (tid & 31) * 4;

    for (int kt = 0; kt < 128; kt += 16) {
#pragma unroll
        for (int r = 0; r < 2; r++) {
            int row = m0 + arow + r * 64;
            float4 v = make_float4(0.f, 0.f, 0.f, 0.f);
            if (row < M) v = *(const float4*)&A[row * 128 + kt + akg];
            As[akg + 0][arow + r * 64] = v.x;
            As[akg + 1][arow + r * 64] = v.y;
            As[akg + 2][arow + r * 64] = v.z;
            As[akg + 3][arow + r * 64] = v.w;
        }
#pragma unroll
        for (int r = 0; r < 2; r++) {
            int krow = brow + r * 8;
            *(float4*)&Bs[krow][bcol] = *(const float4*)&B[(kt + krow) * 512 + n0 + bcol];
        }
        __syncthreads();
#pragma unroll
        for (int k = 0; k < 16; k++) {
            float a[8], b[8];
            *(float4*)&a[0] = *(float4*)&As[k][ty * 8];
            *(float4*)&a[4] = *(float4*)&As[k][ty * 8 + 4];
            *(float4*)&b[0] = *(float4*)&Bs[k][tx * 8];
            *(float4*)&b[4] = *(float4*)&Bs[k][tx * 8 + 4];
#pragma unroll
            for (int i = 0; i < 8; i++)
#pragma unroll
                for (int j = 0; j < 8; j++) acc[i][j] += a[i] * b[j];
        }
        __syncthreads();
    }
#pragma unroll
    for (int i = 0; i < 8; i++) {
        int row = m0 + ty * 8 + i;
        if (row < M) {
            float4 v0 = make_float4(acc[i][0], acc[i][1], acc[i][2], acc[i][3]);
            float4 v1 = make_float4(acc[i][4], acc[i][5], acc[i][6], acc[i][7]);
            *(float4*)&C[row * 512 + n0 + tx * 8]     = v0;
            *(float4*)&C[row * 512 + n0 + tx * 8 + 4] = v1;
        }
    }
}

// ---------------- per-node alpha dot products ----------------
__global__ void k_alpha(const float* __restrict__ aw_s, const float* __restrict__ aw_d) {
    int n = blockIdx.x;
    int tid = threadIdx.x;
    int h = tid >> 5, lane = tid & 31;
    const float* row = &g_hh[n * 512 + h * 128];
    float s1 = 0.f, s2 = 0.f;
#pragma unroll
    for (int j = lane; j < 128; j += 32) {
        float v = row[j];
        s1 += v * aw_s[h * 128 + j];
        s2 += v * aw_d[h * 128 + j];
    }
#pragma unroll
    for (int off = 16; off > 0; off >>= 1) {
        s1 += __shfl_xor_sync(0xffffffffu, s1, off);
        s2 += __shfl_xor_sync(0xffffffffu, s2, off);
    }
    if (lane == 0) { g_as[n * 4 + h] = s1; g_ad[n * 4 + h] = s2; }
}

// ---------------- GAT aggregation + head-mean + bias + LN + relu + residual ----------------
__global__ __launch_bounds__(128) void k_gat(const float* __restrict__ bg,
                                             const float* __restrict__ lnw,
                                             const float* __restrict__ lnb) {
    int node = blockIdx.x, tid = threadIdx.x;
    int h = tid >> 5, lane = tid & 31;
    __shared__ float sm[4], ss[4], sad[4], rbuf[8];
    if (tid < 4) sad[tid] = g_ad[node * 4 + tid];
    int beg = g_rowptr[node], end = g_rowptr[node + 1];
    __syncthreads();

    // pass 1: per-head online softmax stats (warp per head)
    float adh = sad[h];
    float m = -1e30f, s = 0.f;
    for (int e = beg + lane; e < end; e += 32) {
        int src = g_esrc[e];
        float x = g_as[src * 4 + h] + adh;
        x = x > 0.f ? x : 0.2f * x;
        float nm = fmaxf(m, x);
        s = s * __expf(m - nm) + __expf(x - nm);
        m = nm;
    }
#pragma unroll
    for (int off = 16; off > 0; off >>= 1) {
        float mo = __shfl_xor_sync(0xffffffffu, m, off);
        float so = __shfl_xor_sync(0xffffffffu, s, off);
        float nm = fmaxf(m, mo);
        s = s * __expf(m - nm) + so * __expf(mo - nm);
        m = nm;
    }
    if (lane == 0) { sm[h] = m; ss[h] = 1.f / s; }
    __syncthreads();

    float m0 = sm[0], m1 = sm[1], m2 = sm[2], m3 = sm[3];
    float i0 = ss[0], i1 = ss[1], i2 = ss[2], i3 = ss[3];
    float a0 = sad[0], a1 = sad[1], a2 = sad[2], a3 = sad[3];

    // pass 2: weighted gather, thread = feature dim, 4 head accumulators
    float c0 = 0.f, c1 = 0.f, c2 = 0.f, c3 = 0.f;
    for (int e = beg; e < end; e++) {
        int src = g_esrc[e];
        float4 av = *(const float4*)&g_as[src * 4];
        const float* row = &g_hh[src * 512];
        float x0 = av.x + a0; x0 = x0 > 0.f ? x0 : 0.2f * x0;
        float x1 = av.y + a1; x1 = x1 > 0.f ? x1 : 0.2f * x1;
        float x2 = av.z + a2; x2 = x2 > 0.f ? x2 : 0.2f * x2;
        float x3 = av.w + a3; x3 = x3 > 0.f ? x3 : 0.2f * x3;
        float w0 = __expf(x0 - m0) * i0;
        float w1 = __expf(x1 - m1) * i1;
        float w2 = __expf(x2 - m2) * i2;
        float w3 = __expf(x3 - m3) * i3;
        c0 += w0 * row[tid];
        c1 += w1 * row[128 + tid];
        c2 += w2 * row[256 + tid];
        c3 += w3 * row[384 + tid];
    }
    float o = 0.25f * (c0 + c1 + c2 + c3) + bg[tid];

    // layernorm over 128 dims
    float vs = o, vq = o * o;
#pragma unroll
    for (int off = 16; off > 0; off >>= 1) {
        vs += __shfl_xor_sync(0xffffffffu, vs, off);
        vq += __shfl_xor_sync(0xffffffffu, vq, off);
    }
    if (lane == 0) { rbuf[h] = vs; rbuf[4 + h] = vq; }
    __syncthreads();
    float tot  = rbuf[0] + rbuf[1] + rbuf[2] + rbuf[3];
    float tot2 = rbuf[4] + rbuf[5] + rbuf[6] + rbuf[7];
    float mu  = tot * (1.f / 128.f);
    float var = tot2 * (1.f / 128.f) - mu * mu;
    float val = (o - mu) * rsqrtf(var + 1e-5f) * lnw[tid] + lnb[tid];
    g_h[node * DH + tid] += fmaxf(val, 0.f);
}

// ---------------- pooling (batch is sorted -> contiguous segments) ----------------
__global__ void k_pool() {
    int g = blockIdx.x, d = threadIdx.x;
    int beg = g_gstart[g], end = g_gstart[g + 1];
    float s = 0.f, mx = -1e30f;
    for (int i = beg; i < end; i++) {
        float v = g_h[i * DH + d];
        s += v;
        mx = fmaxf(mx, v);
    }
    int cnt = end - beg;
    float denom = (float)(cnt > 0 ? cnt : 1);
    g_pool[g * 320 + d]       = s / denom;
    g_pool[g * 320 + 128 + d] = (cnt > 0) ? mx : 0.f;
}

// ---------------- TDA branch: relu(relu(tda@w1+b1)@w2+b2) ----------------
__global__ void k_tda(const float* __restrict__ tda, const float* __restrict__ w1,
                      const float* __restrict__ b1, const float* __restrict__ w2,
                      const float* __restrict__ b2) {
    int g = blockIdx.x, t = threadIdx.x;   // 64 threads
    __shared__ float ts[FT], h1[64];
    if (t < FT) ts[t] = tda[g * FT + t];
    __syncthreads();
    float a = b1[t];
#pragma unroll
    for (int k = 0; k < FT; k++) a += ts[k] * w1[k * 64 + t];
    h1[t] = fmaxf(a, 0.f);
    __syncthreads();
    float c = b2[t];
#pragma unroll
    for (int k = 0; k < 64; k++) c += h1[k] * w2[k * 64 + t];
    g_pool[g * 320 + 256 + t] = fmaxf(c, 0.f);
}

// ---------------- trunk + task heads ----------------
__global__ __launch_bounds__(256) void k_head(const float* __restrict__ wsh1, const float* __restrict__ bsh1,
                                              const float* __restrict__ wsh2, const float* __restrict__ bsh2,
                                              const float* __restrict__ wh1,  const float* __restrict__ bh1,
                                              const float* __restrict__ wh2,  const float* __restrict__ bh2,
                                              float* __restrict__ out) {
    int g = blockIdx.x, tid = threadIdx.x;
    __shared__ float comb[320], s1[256], s2[128], hh1[NT * 64];
    for (int i = tid; i < 320; i += 256) comb[i] = g_pool[g * 320 + i];
    __syncthreads();
    float a = bsh1[tid];
    for (int k = 0; k < 320; k++) a += comb[k] * wsh1[k * 256 + tid];
    s1[tid] = fmaxf(a, 0.f);
    __syncthreads();
    if (tid < 128) {
        float c = bsh2[tid];
        for (int k = 0; k < 256; k++) c += s1[k] * wsh2[k * 128 + tid];
        s2[tid] = fmaxf(c, 0.f);
    }
    __syncthreads();
    for (int idx = tid; idx < NT * 64; idx += 256) {
        int t = idx >> 6, kk = idx & 63;
        float c = bh1[t * 64 + kk];
        for (int k = 0; k < 128; k++) c += s2[k] * wh1[t * 8192 + k * 64 + kk];
        hh1[idx] = fmaxf(c, 0.f);
    }
    __syncthreads();
    if (tid < NT) {
        float c = bh2[tid];
        for (int k = 0; k < 64; k++) c += hh1[tid * 64 + k] * wh2[tid * 64 + k];
        out[tid * NGR + g] = c;
    }
}

// ---------------- launch ----------------
extern "C" void kernel_launch(void* const* d_in, const int* in_sizes, int n_in,
                              void* d_out, int out_size) {
    const float* x       = (const float*)d_in[0];
    const int*   ei      = (const int*)d_in[1];
    const int*   batch   = (const int*)d_in[2];
    const float* tda     = (const float*)d_in[3];
    const float* w_in    = (const float*)d_in[4];
    const float* b_in    = (const float*)d_in[5];
    const float* w_gat   = (const float*)d_in[6];
    const float* a_src   = (const float*)d_in[7];
    const float* a_dst   = (const float*)d_in[8];
    const float* b_gat   = (const float*)d_in[9];
    const float* ln_w    = (const float*)d_in[10];
    const float* ln_b    = (const float*)d_in[11];
    const float* w_tda1  = (const float*)d_in[12];
    const float* b_tda1  = (const float*)d_in[13];
    const float* w_tda2  = (const float*)d_in[14];
    const float* b_tda2  = (const float*)d_in[15];
    const float* w_sh1   = (const float*)d_in[16];
    const float* b_sh1   = (const float*)d_in[17];
    const float* w_sh2   = (const float*)d_in[18];
    const float* b_sh2   = (const float*)d_in[19];
    const float* w_h1    = (const float*)d_in[20];
    const float* b_h1    = (const float*)d_in[21];
    const float* w_h2    = (const float*)d_in[22];
    const float* b_h2    = (const float*)d_in[23];
    float* out = (float*)d_out;

    // CSR by dst (includes self loops)
    k_zero_cnt<<<(NN + 255) / 256, 256>>>();
    k_count<<<(ETOT + 255) / 256, 256>>>(ei);
    k_scan<<<1, 1024>>>();
    k_cursor<<<(NN + 255) / 256, 256>>>();
    k_scatter<<<(ETOT + 255) / 256, 256>>>(ei);
    k_gstart<<<(NN + 256) / 256, 256>>>(batch);

    // input projection
    k_inproj<<<NN, 128>>>(x, w_in, b_in);

    // GAT layers
    for (int l = 0; l < NL; l++) {
        k_gemm<<<dim3((NN + 127) / 128, 4), 256>>>(w_gat + l * 128 * 512);
        k_alpha<<<NN, 128>>>(a_src + l * 512, a_dst + l * 512);
        k_gat<<<NN, 128>>>(b_gat + l * 128, ln_w + l * 128, ln_b + l * 128);
    }

    // pooling + TDA + heads
    k_pool<<<NGR, 128>>>();
    k_tda<<<NGR, 64>>>(tda, w_tda1, b_tda1, w_tda2, b_tda2);
    k_head<<<NGR, 256>>>(w_sh1, b_sh1, w_sh2, b_sh2, w_h1, b_h1, w_h2, b_h2, out);
}

// round 3
// speedup vs baseline: 1.5268x; 1.5268x over previous
#include <cuda_runtime.h>
#include <math.h>

#define NN   20000        // nodes
#define NE   320000       // edges (without self loops)
#define ETOT (NE + NN)    // edges + self loops
#define NGR  256          // graphs
#define FD   11           // node feature dim
#define FT   30           // tda feature dim
#define DH   128          // hidden
#define NH   4            // heads
#define NL   3            // layers
#define NT   6            // tasks

// ---------------- device scratch (static, no allocations) ----------------
// Referenced ONLY inside kernels — never passed as kernel arguments.
__device__ float g_h[NN * DH];            // node features (in-place updated)
__device__ float g_hh[NN * NH * DH];      // per-head transformed features [N,512]
__device__ float g_as[NN * NH];           // alpha_src per node/head
__device__ float g_ad[NN * NH];           // alpha_dst per node/head
__device__ int   g_rowptr[NN + 1];
__device__ int   g_cnt[NN];               // counts, then scatter cursor
__device__ int   g_esrc[ETOT];            // src ids sorted by dst
__device__ int   g_gstart[NGR + 1];
__device__ float g_pool[NGR * 320];       // [mean(128) | max(128) | tda(64)]

// ---------------- tf32 mma helpers ----------------
__device__ __forceinline__ void mma_tf32(float c[4], const unsigned a[4], const unsigned b[2]) {
    asm volatile(
        "mma.sync.aligned.m16n8k8.row.col.f32.tf32.tf32.f32 "
        "{%0,%1,%2,%3}, {%4,%5,%6,%7}, {%8,%9}, {%0,%1,%2,%3};\n"
        : "+f"(c[0]), "+f"(c[1]), "+f"(c[2]), "+f"(c[3])
        : "r"(a[0]), "r"(a[1]), "r"(a[2]), "r"(a[3]), "r"(b[0]), "r"(b[1]));
}

__device__ __forceinline__ void split_tf32(float x, unsigned& hi, unsigned& lo) {
    unsigned h_;
    asm("cvt.rna.tf32.f32 %0, %1;" : "=r"(h_) : "f"(x));
    float l = x - __uint_as_float(h_);
    unsigned l_;
    asm("cvt.rna.tf32.f32 %0, %1;" : "=r"(l_) : "f"(l));
    hi = h_; lo = l_;
}

// ---------------- CSR build ----------------
__global__ void k_prep(const int* __restrict__ batch) {
    int i = blockIdx.x * blockDim.x + threadIdx.x;
    if (i < NN) g_cnt[i] = 0;
    if (i <= NN) {
        int b  = (i < NN) ? batch[i] : NGR;
        int bp = (i > 0) ? batch[i - 1] : -1;
        for (int g = bp + 1; g <= b && g <= NGR; g++) g_gstart[g] = i;
    }
}

__global__ void k_count(const int* __restrict__ ei) {
    int i = blockIdx.x * blockDim.x + threadIdx.x;
    if (i >= ETOT) return;
    int dst = (i < NE) ? ei[NE + i] : (i - NE);
    atomicAdd(&g_cnt[dst], 1);
}

__global__ void k_scan() {   // single block, 1024 threads, chunk=20; also writes cursor
    __shared__ int ssum[1024];
    const int CH = 20;
    int tid = threadIdx.x;
    int base = tid * CH;
    int s = 0;
    for (int j = 0; j < CH; j++) {
        int idx = base + j;
        if (idx < NN) s += g_cnt[idx];
    }
    ssum[tid] = s;
    __syncthreads();
    for (int off = 1; off < 1024; off <<= 1) {
        int v = 0;
        if (tid >= off) v = ssum[tid - off];
        __syncthreads();
        ssum[tid] += v;
        __syncthreads();
    }
    int run = tid ? ssum[tid - 1] : 0;
    for (int j = 0; j < CH; j++) {
        int idx = base + j;
        if (idx < NN) {
            int c = g_cnt[idx];
            g_rowptr[idx] = run;
            g_cnt[idx]    = run;   // scatter cursor
            run += c;
        }
    }
    if (tid == 1023) g_rowptr[NN] = ssum[1023];
}

__global__ void k_scatter(const int* __restrict__ ei) {
    int i = blockIdx.x * blockDim.x + threadIdx.x;
    if (i >= ETOT) return;
    int src, dst;
    if (i < NE) { src = ei[i]; dst = ei[NE + i]; }
    else        { src = i - NE; dst = i - NE; }
    int pos = atomicAdd(&g_cnt[dst], 1);
    g_esrc[pos] = src;
}

// ---------------- input projection: h = relu(x @ w_in + b_in) ----------------
__global__ void k_inproj(const float* __restrict__ x, const float* __restrict__ w,
                         const float* __restrict__ b) {
    int n = blockIdx.x, d = threadIdx.x;
    __shared__ float xs[FD];
    if (d < FD) xs[d] = x[n * FD + d];
    __syncthreads();
    float a = b[d];
#pragma unroll
    for (int k = 0; k < FD; k++) a += xs[k] * w[k * DH + d];
    g_h[n * DH + d] = fmaxf(a, 0.f);
}

// ---------------- tf32 tensor-core GEMM + fused alpha dots ----------------
// block: 128 rows x one head (128 cols). grid (157, 4). 256 threads = 8 warps (4m x 2n).
__global__ __launch_bounds__(256) void k_gemm_tc(const float* __restrict__ B,
                                                 const float* __restrict__ aw_s,
                                                 const float* __restrict__ aw_d) {
    __shared__ float As[128][36];
    __shared__ float Bs[32][132];
    __shared__ float s_as[128], s_ad[128];
    __shared__ float abuf[2][2][128];   // [s/d][warp_n][row]

    int tid = threadIdx.x;
    int wid = tid >> 5, lane = tid & 31;
    int warp_m = wid & 3, warp_n = wid >> 2;
    int m0 = blockIdx.x * 128;
    int h  = blockIdx.y;
    int g  = lane >> 2, t = lane & 3;

    if (tid < 128) { s_as[tid] = aw_s[h * 128 + tid]; s_ad[tid] = aw_d[h * 128 + tid]; }

    float c[2][8][4];
#pragma unroll
    for (int mt = 0; mt < 2; mt++)
#pragma unroll
        for (int nt = 0; nt < 8; nt++)
#pragma unroll
            for (int i = 0; i < 4; i++) c[mt][nt][i] = 0.f;

    int ar = tid >> 1, akg = (tid & 1) * 16;
    int bkr = tid >> 3, bcg = (tid & 7) * 16;

    for (int kc = 0; kc < 128; kc += 32) {
        __syncthreads();
        if (m0 + ar < NN) {
#pragma unroll
            for (int j = 0; j < 4; j++)
                *(float4*)&As[ar][akg + j * 4] =
                    *(const float4*)&g_h[(m0 + ar) * 128 + kc + akg + j * 4];
        } else {
            float4 z = make_float4(0.f, 0.f, 0.f, 0.f);
#pragma unroll
            for (int j = 0; j < 4; j++) *(float4*)&As[ar][akg + j * 4] = z;
        }
#pragma unroll
        for (int j = 0; j < 4; j++)
            *(float4*)&Bs[bkr][bcg + j * 4] =
                *(const float4*)&B[(kc + bkr) * 512 + h * 128 + bcg + j * 4];
        __syncthreads();

#pragma unroll
        for (int kk = 0; kk < 32; kk += 8) {
            unsigned ah[2][4], al[2][4];
#pragma unroll
            for (int mt = 0; mt < 2; mt++) {
                int rb = warp_m * 32 + mt * 16;
                float a0 = As[rb + g][kk + t];
                float a1 = As[rb + g + 8][kk + t];
                float a2 = As[rb + g][kk + t + 4];
                float a3 = As[rb + g + 8][kk + t + 4];
                split_tf32(a0, ah[mt][0], al[mt][0]);
                split_tf32(a1, ah[mt][1], al[mt][1]);
                split_tf32(a2, ah[mt][2], al[mt][2]);
                split_tf32(a3, ah[mt][3], al[mt][3]);
            }
#pragma unroll
            for (int nt = 0; nt < 8; nt++) {
                int cb = warp_n * 64 + nt * 8;
                float b0 = Bs[kk + t][cb + g];
                float b1 = Bs[kk + t + 4][cb + g];
                unsigned bh[2], bl[2];
                split_tf32(b0, bh[0], bl[0]);
                split_tf32(b1, bh[1], bl[1]);
#pragma unroll
                for (int mt = 0; mt < 2; mt++) {
                    mma_tf32(c[mt][nt], ah[mt], bh);
                    mma_tf32(c[mt][nt], ah[mt], bl);
                    mma_tf32(c[mt][nt], al[mt], bh);
                }
            }
        }
    }

    // epilogue: store C to g_hh + fused alpha partial dots
    float ps[4] = {0.f, 0.f, 0.f, 0.f}, pd[4] = {0.f, 0.f, 0.f, 0.f};
#pragma unroll
    for (int mt = 0; mt < 2; mt++) {
        int row0 = warp_m * 32 + mt * 16 + g;
        int row1 = row0 + 8;
#pragma unroll
        for (int nt = 0; nt < 8; nt++) {
            int col = warp_n * 64 + nt * 8 + t * 2;
            float c0 = c[mt][nt][0], c1 = c[mt][nt][1];
            float c2 = c[mt][nt][2], c3 = c[mt][nt][3];
            if (m0 + row0 < NN) {
                float2 v = make_float2(c0, c1);
                *(float2*)&g_hh[(m0 + row0) * 512 + h * 128 + col] = v;
            }
            if (m0 + row1 < NN) {
                float2 v = make_float2(c2, c3);
                *(float2*)&g_hh[(m0 + row1) * 512 + h * 128 + col] = v;
            }
            float w0 = s_as[col], w1 = s_as[col + 1];
            float d0 = s_ad[col], d1 = s_ad[col + 1];
            ps[mt * 2 + 0] += c0 * w0 + c1 * w1;
            ps[mt * 2 + 1] += c2 * w0 + c3 * w1;
            pd[mt * 2 + 0] += c0 * d0 + c1 * d1;
            pd[mt * 2 + 1] += c2 * d0 + c3 * d1;
        }
    }
#pragma unroll
    for (int off = 1; off <= 2; off <<= 1) {
#pragma unroll
        for (int i = 0; i < 4; i++) {
            ps[i] += __shfl_xor_sync(0xffffffffu, ps[i], off);
            pd[i] += __shfl_xor_sync(0xffffffffu, pd[i], off);
        }
    }
    if (t == 0) {
#pragma unroll
        for (int mt = 0; mt < 2; mt++)
#pragma unroll
            for (int hf = 0; hf < 2; hf++) {
                int row = warp_m * 32 + mt * 16 + hf * 8 + g;
                abuf[0][warp_n][row] = ps[mt * 2 + hf];
                abuf[1][warp_n][row] = pd[mt * 2 + hf];
            }
    }
    __syncthreads();
    if (tid < 128 && m0 + tid < NN) {
        g_as[(m0 + tid) * 4 + h] = abuf[0][0][tid] + abuf[0][1][tid];
        g_ad[(m0 + tid) * 4 + h] = abuf[1][0][tid] + abuf[1][1][tid];
    }
}

// ---------------- GAT aggregation + head-mean + bias + LN + relu + residual ----------------
__global__ __launch_bounds__(128) void k_gat(const float* __restrict__ bg,
                                             const float* __restrict__ lnw,
                                             const float* __restrict__ lnb) {
    int node = blockIdx.x, tid = threadIdx.x;
    int h = tid >> 5, lane = tid & 31;
    __shared__ float sm[4], ss[4], sad[4], rbuf[8];
    __shared__ int   ssrc[32];
    __shared__ float swt[32][4];
    if (tid < 4) sad[tid] = g_ad[node * 4 + tid];
    int beg = g_rowptr[node], end = g_rowptr[node + 1];
    __syncthreads();

    // pass 1: per-head online softmax stats (warp per head)
    float adh = sad[h];
    float m = -1e30f, s = 0.f;
    for (int e = beg + lane; e < end; e += 32) {
        int src = g_esrc[e];
        float x = g_as[src * 4 + h] + adh;
        x = x > 0.f ? x : 0.2f * x;
        float nm = fmaxf(m, x);
        s = s * __expf(m - nm) + __expf(x - nm);
        m = nm;
    }
#pragma unroll
    for (int off = 16; off > 0; off >>= 1) {
        float mo = __shfl_xor_sync(0xffffffffu, m, off);
        float so = __shfl_xor_sync(0xffffffffu, s, off);
        float nm = fmaxf(m, mo);
        s = s * __expf(m - nm) + so * __expf(mo - nm);
        m = nm;
    }
    if (lane == 0) { sm[h] = m; ss[h] = 1.f / s; }
    __syncthreads();

    // pass 2: chunked — compute each edge/head weight exactly once
    float c0 = 0.f, c1 = 0.f, c2 = 0.f, c3 = 0.f;
    for (int base = beg; base < end; base += 32) {
        int cnt = end - base; if (cnt > 32) cnt = 32;
        if (tid < cnt * 4) {
            int e  = base + (tid >> 2);
            int hd = tid & 3;
            int src = g_esrc[e];
            float x = g_as[src * 4 + hd] + sad[hd];
            x = x > 0.f ? x : 0.2f * x;
            swt[tid >> 2][hd] = __expf(x - sm[hd]) * ss[hd];
            if (hd == 0) ssrc[tid >> 2] = src;
        }
        __syncthreads();
        for (int j = 0; j < cnt; j++) {
            int src = ssrc[j];
            float4 w = *(const float4*)swt[j];
            const float* row = &g_hh[src * 512];
            c0 += w.x * row[tid];
            c1 += w.y * row[128 + tid];
            c2 += w.z * row[256 + tid];
            c3 += w.w * row[384 + tid];
        }
        __syncthreads();
    }
    float o = 0.25f * (c0 + c1 + c2 + c3) + bg[tid];

    // layernorm over 128 dims
    float vs = o, vq = o * o;
#pragma unroll
    for (int off = 16; off > 0; off >>= 1) {
        vs += __shfl_xor_sync(0xffffffffu, vs, off);
        vq += __shfl_xor_sync(0xffffffffu, vq, off);
    }
    if (lane == 0) { rbuf[h] = vs; rbuf[4 + h] = vq; }
    __syncthreads();
    float tot  = rbuf[0] + rbuf[1] + rbuf[2] + rbuf[3];
    float tot2 = rbuf[4] + rbuf[5] + rbuf[6] + rbuf[7];
    float mu  = tot * (1.f / 128.f);
    float var = tot2 * (1.f / 128.f) - mu * mu;
    float val = (o - mu) * rsqrtf(var + 1e-5f) * lnw[tid] + lnb[tid];
    g_h[node * DH + tid] += fmaxf(val, 0.f);
}

// ---------------- pooling (batch is sorted -> contiguous segments) ----------------
__global__ void k_pool() {
    int g = blockIdx.x, d = threadIdx.x;
    int beg = g_gstart[g], end = g_gstart[g + 1];
    float s = 0.f, mx = -1e30f;
    for (int i = beg; i < end; i++) {
        float v = g_h[i * DH + d];
        s += v;
        mx = fmaxf(mx, v);
    }
    int cnt = end - beg;
    float denom = (float)(cnt > 0 ? cnt : 1);
    g_pool[g * 320 + d]       = s / denom;
    g_pool[g * 320 + 128 + d] = (cnt > 0) ? mx : 0.f;
}

// ---------------- TDA branch ----------------
__global__ void k_tda(const float* __restrict__ tda, const float* __restrict__ w1,
                      const float* __restrict__ b1, const float* __restrict__ w2,
                      const float* __restrict__ b2) {
    int g = blockIdx.x, t = threadIdx.x;   // 64 threads
    __shared__ float ts[FT], h1[64];
    if (t < FT) ts[t] = tda[g * FT + t];
    __syncthreads();
    float a = b1[t];
#pragma unroll
    for (int k = 0; k < FT; k++) a += ts[k] * w1[k * 64 + t];
    h1[t] = fmaxf(a, 0.f);
    __syncthreads();
    float c = b2[t];
#pragma unroll
    for (int k = 0; k < 64; k++) c += h1[k] * w2[k * 64 + t];
    g_pool[g * 320 + 256 + t] = fmaxf(c, 0.f);
}

// ---------------- trunk + task heads ----------------
__global__ __launch_bounds__(256) void k_head(const float* __restrict__ wsh1, const float* __restrict__ bsh1,
                                              const float* __restrict__ wsh2, const float* __restrict__ bsh2,
                                              const float* __restrict__ wh1,  const float* __restrict__ bh1,
                                              const float* __restrict__ wh2,  const float* __restrict__ bh2,
                                              float* __restrict__ out) {
    int g = blockIdx.x, tid = threadIdx.x;
    __shared__ float comb[320], s1[256], s2[128], hh1[NT * 64];
    for (int i = tid; i < 320; i += 256) comb[i] = g_pool[g * 320 + i];
    __syncthreads();
    float a = bsh1[tid];
    for (int k = 0; k < 320; k++) a += comb[k] * wsh1[k * 256 + tid];
    s1[tid] = fmaxf(a, 0.f);
    __syncthreads();
    if (tid < 128) {
        float c = bsh2[tid];
        for (int k = 0; k < 256; k++) c += s1[k] * wsh2[k * 128 + tid];
        s2[tid] = fmaxf(c, 0.f);
    }
    __syncthreads();
    for (int idx = tid; idx < NT * 64; idx += 256) {
        int t = idx >> 6, kk = idx & 63;
        float c = bh1[t * 64 + kk];
        for (int k = 0; k < 128; k++) c += s2[k] * wh1[t * 8192 + k * 64 + kk];
        hh1[idx] = fmaxf(c, 0.f);
    }
    __syncthreads();
    if (tid < NT) {
        float c = bh2[tid];
        for (int k = 0; k < 64; k++) c += hh1[tid * 64 + k] * wh2[tid * 64 + k];
        out[tid * NGR + g] = c;
    }
}

// ---------------- launch ----------------
extern "C" void kernel_launch(void* const* d_in, const int* in_sizes, int n_in,
                              void* d_out, int out_size) {
    const float* x       = (const float*)d_in[0];
    const int*   ei      = (const int*)d_in[1];
    const int*   batch   = (const int*)d_in[2];
    const float* tda     = (const float*)d_in[3];
    const float* w_in    = (const float*)d_in[4];
    const float* b_in    = (const float*)d_in[5];
    const float* w_gat   = (const float*)d_in[6];
    const float* a_src   = (const float*)d_in[7];
    const float* a_dst   = (const float*)d_in[8];
    const float* b_gat   = (const float*)d_in[9];
    const float* ln_w    = (const float*)d_in[10];
    const float* ln_b    = (const float*)d_in[11];
    const float* w_tda1  = (const float*)d_in[12];
    const float* b_tda1  = (const float*)d_in[13];
    const float* w_tda2  = (const float*)d_in[14];
    const float* b_tda2  = (const float*)d_in[15];
    const float* w_sh1   = (const float*)d_in[16];
    const float* b_sh1   = (const float*)d_in[17];
    const float* w_sh2   = (const float*)d_in[18];
    const float* b_sh2   = (const float*)d_in[19];
    const float* w_h1    = (const float*)d_in[20];
    const float* b_h1    = (const float*)d_in[21];
    const float* w_h2    = (const float*)d_in[22];
    const float* b_h2    = (const float*)d_in[23];
    float* out = (float*)d_out;

    // CSR by dst (includes self loops) + graph boundaries
    k_prep<<<(NN + 256) / 256, 256>>>(batch);
    k_count<<<(ETOT + 255) / 256, 256>>>(ei);
    k_scan<<<1, 1024>>>();
    k_scatter<<<(ETOT + 255) / 256, 256>>>(ei);

    // input projection
    k_inproj<<<NN, 128>>>(x, w_in, b_in);

    // GAT layers
    for (int l = 0; l < NL; l++) {
        k_gemm_tc<<<dim3((NN + 127) / 128, 4), 256>>>(w_gat + l * 128 * 512,
                                                      a_src + l * 512, a_dst + l * 512);
        k_gat<<<NN, 128>>>(b_gat + l * 128, ln_w + l * 128, ln_b + l * 128);
    }

    // pooling + TDA + heads
    k_pool<<<NGR, 128>>>();
    k_tda<<<NGR, 64>>>(tda, w_tda1, b_tda1, w_tda2, b_tda2);
    k_head<<<NGR, 256>>>(w_sh1, b_sh1, w_sh2, b_sh2, w_h1, b_h1, w_h2, b_h2, out);
}